// round 9
// baseline (speedup 1.0000x reference)
#include <cuda_runtime.h>
#include <cuda_bf16.h>

// EmbeddedGCN: out[b,i,o] = relu( sum_j adj[b,i,j] * (concat(s1,s2)[b,i,j,:] @ W)[o] + bias[o] )
// Linearity rewrite:
//   y[b,i,f]   = sum_j adj[b,i,j] * concat(s1,s2)[b,i,j,f]     (gated gather-reduce)
//   out[b,i,o] = relu( sum_f y[f]*W[f,o] + bias[o]*rowsum(adj) )
//
// B=16, M=128, FE=64 (concat 128), FO=128.
// cp.async gather: one warp per row stages up to 32 neighbor rows (16 KB) into
// smem per chunk with zero register residency, then reduces. Per-lane cp.async
// self-visibility -> no barrier in phase 1. RPB=4, 128-thread blocks,
// ~71.7 KB dyn smem -> 3 blocks/SM for phase overlap.

#define BM 128
#define FE 64
#define FT 128
#define FO 128
#define RPB 4
#define SLOTS 32
#define THREADS 128

// dynamic smem layout (bytes):
//   staging : RPB*SLOTS*512          = 65536
//   jidx    : RPB*BM*4               =  2048
//   aval    : RPB*BM*4               =  2048
//   y       : RPB*FT*4               =  2048
//   rowsum  : RPB*4 (+pad)           =    32
#define SMEM_BYTES (RPB*SLOTS*512 + RPB*BM*4 + RPB*BM*4 + RPB*FT*4 + 32)

__global__ void __launch_bounds__(THREADS, 3)
gcn_cp(const float* __restrict__ s1,
       const float* __restrict__ s2,
       const float* __restrict__ adj,
       const float* __restrict__ W,
       const float* __restrict__ bias,
       float* __restrict__ out)
{
    extern __shared__ char smem[];
    float* staging  = (float*)smem;                                  // [RPB*SLOTS*128]
    int*   jidx_s   = (int*)(smem + RPB * SLOTS * 512);
    float* aval_s   = (float*)((char*)jidx_s + RPB * BM * 4);
    float* y_s      = aval_s + RPB * BM;
    float* rowsum_s = y_s + RPB * FT;

    const int tid  = threadIdx.x;        // 0..127
    const int lane = tid & 31;
    const int w    = tid >> 5;           // warp id = local row 0..3
    const int bi0  = blockIdx.x * RPB;
    const int row  = bi0 + w;            // flat b*M + i

    // ---- Phase 1a: adjacency load + warp-prefix compaction (one warp per row) ----
    const float4 av = *(const float4*)(adj + (size_t)row * BM + lane * 4);
    int   cnt  = 0;
    float rsum = 0.0f;
    {
        const unsigned lt = (1u << lane) - 1u;
        #pragma unroll
        for (int q = 0; q < 4; q++) {
            const float a = (q == 0) ? av.x : (q == 1) ? av.y : (q == 2) ? av.z : av.w;
            const unsigned m = __ballot_sync(0xFFFFFFFFu, a != 0.0f);
            if (a != 0.0f) {
                const int pos = cnt + __popc(m & lt);
                jidx_s[w * BM + pos] = lane * 4 + q;
                aval_s[w * BM + pos] = a;
            }
            cnt  += __popc(m);
            rsum += a;
        }
        #pragma unroll
        for (int off = 16; off > 0; off >>= 1)
            rsum += __shfl_xor_sync(0xFFFFFFFFu, rsum, off);
        if (lane == 0) rowsum_s[w] = rsum;
    }
    __syncwarp();

    // ---- Phase 1b: cp.async staged gather-reduce ----
    // lane -> one 16B chunk of the 128-wide concat row:
    //   lanes 0..15  -> s1, float4 idx = lane        (features 0..63)
    //   lanes 16..31 -> s2, float4 idx = lane - 16   (features 64..127)
    const float4* base4;
    {
        const size_t row0 = (size_t)row * (size_t)(BM * FE);
        base4 = (lane < 16) ? ((const float4*)(s1 + row0) + lane)
                            : ((const float4*)(s2 + row0) + (lane - 16));
    }
    // per-(warp,lane) staging base, u32 shared address; slot k at +k*512
    const unsigned stag_u32 =
        (unsigned)__cvta_generic_to_shared(staging + (size_t)w * SLOTS * 128 + lane * 4);
    const float* stag_f = staging + (size_t)w * SLOTS * 128 + lane * 4;

    float4 acc = make_float4(0.f, 0.f, 0.f, 0.f);

    for (int k0 = 0; k0 < cnt; k0 += SLOTS) {
        // Issue 32 predicated 16B cp.asyncs: invalid slots use src-size=0 (pure
        // zero-fill, no gmem access). All in flight at once (16 KB/warp).
        #pragma unroll
        for (int k = 0; k < SLOTS; k++) {
            const int  kk  = k0 + k;
            const bool val = kk < cnt;
            const int  j   = val ? jidx_s[w * BM + kk] : 0;
            const float4* src = base4 + (size_t)j * 16;   // j*256B in float4 units
            const unsigned ssz = val ? 16u : 0u;
            const unsigned dst = stag_u32 + (unsigned)(k * 512);
            asm volatile("cp.async.cg.shared.global [%0], [%1], 16, %2;\n"
                         :: "r"(dst), "l"(src), "r"(ssz) : "memory");
        }
        asm volatile("cp.async.commit_group;\n" ::: "memory");
        asm volatile("cp.async.wait_group 0;\n" ::: "memory");
        // Each lane reads exactly the bytes it copied -> no sync needed.
        #pragma unroll
        for (int k = 0; k < SLOTS; k++) {
            const int   kk = k0 + k;
            const float a  = (kk < cnt) ? aval_s[w * BM + kk] : 0.0f;
            const float4 v = *(const float4*)(stag_f + k * 128);
            acc.x = fmaf(a, v.x, acc.x);
            acc.y = fmaf(a, v.y, acc.y);
            acc.z = fmaf(a, v.z, acc.z);
            acc.w = fmaf(a, v.w, acc.w);
        }
    }

    {
        const int fb = (lane < 16) ? (lane * 4) : (FE + (lane - 16) * 4);
        *(float4*)&y_s[w * FT + fb] = acc;
    }
    __syncthreads();

    // ---- Phase 2: out[q,o] = relu( y[q,:] @ W[:,o] + bias[o]*rowsum[q] ) ----
    // 128 threads: thread owns column o = tid for all RPB rows (W reuse x4).
    const int o = tid;
    float accO[RPB];
    {
        const float bo = __ldg(bias + o);
        #pragma unroll
        for (int q = 0; q < RPB; q++) accO[q] = bo * rowsum_s[q];
    }

    #pragma unroll 8
    for (int f = 0; f < FT; f += 4) {
        const float w0 = __ldg(W + (f + 0) * FO + o);
        const float w1 = __ldg(W + (f + 1) * FO + o);
        const float w2 = __ldg(W + (f + 2) * FO + o);
        const float w3 = __ldg(W + (f + 3) * FO + o);
        #pragma unroll
        for (int q = 0; q < RPB; q++) {
            const float4 y = *(const float4*)&y_s[q * FT + f];
            accO[q] = fmaf(y.x, w0, accO[q]);
            accO[q] = fmaf(y.y, w1, accO[q]);
            accO[q] = fmaf(y.z, w2, accO[q]);
            accO[q] = fmaf(y.w, w3, accO[q]);
        }
    }

    #pragma unroll
    for (int q = 0; q < RPB; q++)
        out[(size_t)(bi0 + q) * FO + o] = fmaxf(accO[q], 0.0f);
}

extern "C" void kernel_launch(void* const* d_in, const int* in_sizes, int n_in,
                              void* d_out, int out_size)
{
    const float* s1   = (const float*)d_in[0];  // (16,128,128,64)
    const float* s2   = (const float*)d_in[1];  // (16,128,128,64)
    const float* adj  = (const float*)d_in[2];  // (16,128,128)
    const float* W    = (const float*)d_in[3];  // (128,128)
    const float* bias = (const float*)d_in[4];  // (128,)
    float* out = (float*)d_out;                 // (16,128,128)

    cudaFuncSetAttribute(gcn_cp, cudaFuncAttributeMaxDynamicSharedMemorySize, SMEM_BYTES);
    gcn_cp<<<(16 * 128) / RPB, THREADS, SMEM_BYTES>>>(s1, s2, adj, W, bias, out);
}

// round 10
// speedup vs baseline: 1.5686x; 1.5686x over previous
#include <cuda_runtime.h>
#include <cuda_bf16.h>

// EmbeddedGCN: out[b,i,o] = relu( sum_j adj[b,i,j] * (concat(s1,s2)[b,i,j,:] @ W)[o] + bias[o] )
// Linearity rewrite:
//   y[b,i,f]   = sum_j adj[b,i,j] * concat(s1,s2)[b,i,j,f]     (gated gather-reduce)
//   out[b,i,o] = relu( sum_f y[f]*W[f,o] + bias[o]*rowsum(adj) )
//
// B=16, M=128, FE=64 (concat -> 128), FO=128.
// R3 skeleton (best so far): 256 threads, 8 warps, one warp per row, RPB=8,
// grid 256. Change vs R3: gather uses a two-deep pipeline of 8-wide batches
// (effective MLP-16) -> dependent DRAM rounds per row drop from 4 to ~2.

#define BM 128
#define FE 64
#define FT 128
#define FO 128
#define RPB 8     // rows per block

__global__ __launch_bounds__(256, 2)
void gcn_fused5(const float* __restrict__ s1,
                const float* __restrict__ s2,
                const float* __restrict__ adj,
                const float* __restrict__ W,
                const float* __restrict__ bias,
                float* __restrict__ out)
{
    __shared__ int   jidx_s[RPB][BM];
    __shared__ float aval_s[RPB][BM];
    __shared__ float y_s[RPB][FT];
    __shared__ float rowsum_s[RPB];

    const int tid  = threadIdx.x;     // 0..255
    const int lane = tid & 31;
    const int w    = tid >> 5;        // warp id = local row id, 0..7
    const int bi0  = blockIdx.x * RPB;
    const int row  = bi0 + w;         // flat b*M + i

    // ---- Phase 1a: adjacency load + warp-prefix compaction ----
    const float4 av = *(const float4*)(adj + (size_t)row * BM + lane * 4);
    int   cnt  = 0;
    float rsum = 0.0f;
    {
        const unsigned lt = (1u << lane) - 1u;
        #pragma unroll
        for (int q = 0; q < 4; q++) {
            const float a = (q == 0) ? av.x : (q == 1) ? av.y : (q == 2) ? av.z : av.w;
            const unsigned m = __ballot_sync(0xFFFFFFFFu, a != 0.0f);
            if (a != 0.0f) {
                const int pos = cnt + __popc(m & lt);
                jidx_s[w][pos] = lane * 4 + q;
                aval_s[w][pos] = a;
            }
            cnt  += __popc(m);
            rsum += a;
        }
        #pragma unroll
        for (int off = 16; off > 0; off >>= 1)
            rsum += __shfl_xor_sync(0xFFFFFFFFu, rsum, off);
        if (lane == 0) rowsum_s[w] = rsum;
    }
    __syncwarp();

    // ---- Phase 1b: gather-reduce, two-deep pipeline of 8-wide batches ----
    // lane -> one float4 of the 128-wide concat row:
    //   lanes 0..15  -> s1, float4 idx = lane        (features 0..63)
    //   lanes 16..31 -> s2, float4 idx = lane - 16   (features 64..127)
    const float4* base4;
    {
        const size_t row0 = (size_t)row * (size_t)(BM * FE);
        base4 = (lane < 16) ? ((const float4*)(s1 + row0) + lane)
                            : ((const float4*)(s2 + row0) + (lane - 16));
    }
    const int jsafe = jidx_s[w][0];   // dummy target for invalid slots (L1 hit)

    float4 v0[8], v1[8];

    // issue batch starting at slot k0 into buf (predicated by cnt)
    #define ISSUE(buf, k0)                                              \
        {                                                               \
            _Pragma("unroll")                                           \
            for (int t = 0; t < 8; t++) {                               \
                const int  kk = (k0) + t;                               \
                const int  j  = (kk < cnt) ? jidx_s[w][kk] : jsafe;     \
                buf[t] = __ldg(base4 + (size_t)j * 16);                 \
            }                                                           \
        }

    // consume batch starting at slot k0 from buf (a=0 for invalid slots)
    #define CONSUME(buf, k0)                                            \
        {                                                               \
            _Pragma("unroll")                                           \
            for (int t = 0; t < 8; t++) {                               \
                const int   kk = (k0) + t;                              \
                const float a  = (kk < cnt) ? aval_s[w][kk] : 0.0f;     \
                acc.x = fmaf(a, buf[t].x, acc.x);                       \
                acc.y = fmaf(a, buf[t].y, acc.y);                       \
                acc.z = fmaf(a, buf[t].z, acc.z);                       \
                acc.w = fmaf(a, buf[t].w, acc.w);                       \
            }                                                           \
        }

    float4 acc = make_float4(0.f, 0.f, 0.f, 0.f);

    ISSUE(v0, 0)
    ISSUE(v1, 8)
    for (int k0 = 0; k0 < cnt; k0 += 16) {
        CONSUME(v0, k0)
        ISSUE(v0, k0 + 16)
        CONSUME(v1, k0 + 8)
        ISSUE(v1, k0 + 24)
    }
    #undef ISSUE
    #undef CONSUME

    {
        const int fb = (lane < 16) ? (lane * 4) : (FE + (lane - 16) * 4);
        *(float4*)&y_s[w][fb] = acc;
    }
    __syncthreads();

    // ---- Phase 2: out[r,o] = relu( y[r,:] @ W[:,o] + bias[o]*rowsum[r] ) ----
    // 256 threads: o = tid&127, group g = tid>>7 owns 4 rows (W reuse x8/block).
    const int o  = tid & (FO - 1);
    const int g  = tid >> 7;          // 0 or 1
    const int r0 = g * 4;

    float accO[4];
    {
        const float bo = __ldg(bias + o);
        #pragma unroll
        for (int q = 0; q < 4; q++) accO[q] = bo * rowsum_s[r0 + q];
    }

    #pragma unroll 8
    for (int f = 0; f < FT; f += 4) {
        const float w0 = __ldg(W + (f + 0) * FO + o);
        const float w1 = __ldg(W + (f + 1) * FO + o);
        const float w2 = __ldg(W + (f + 2) * FO + o);
        const float w3 = __ldg(W + (f + 3) * FO + o);
        #pragma unroll
        for (int q = 0; q < 4; q++) {
            const float4 y = *(const float4*)&y_s[r0 + q][f];
            accO[q] = fmaf(y.x, w0, accO[q]);
            accO[q] = fmaf(y.y, w1, accO[q]);
            accO[q] = fmaf(y.z, w2, accO[q]);
            accO[q] = fmaf(y.w, w3, accO[q]);
        }
    }

    #pragma unroll
    for (int q = 0; q < 4; q++)
        out[(size_t)(bi0 + r0 + q) * FO + o] = fmaxf(accO[q], 0.0f);
}

extern "C" void kernel_launch(void* const* d_in, const int* in_sizes, int n_in,
                              void* d_out, int out_size)
{
    const float* s1   = (const float*)d_in[0];  // (16,128,128,64)
    const float* s2   = (const float*)d_in[1];  // (16,128,128,64)
    const float* adj  = (const float*)d_in[2];  // (16,128,128)
    const float* W    = (const float*)d_in[3];  // (128,128)
    const float* bias = (const float*)d_in[4];  // (128,)
    float* out = (float*)d_out;                 // (16,128,128)

    gcn_fused5<<<(16 * 128) / RPB, 256>>>(s1, s2, adj, W, bias, out);
}

// round 11
// speedup vs baseline: 1.5802x; 1.0074x over previous
#include <cuda_runtime.h>
#include <cuda_bf16.h>

// EmbeddedGCN: out[b,i,o] = relu( sum_j adj[b,i,j] * (concat(s1,s2)[b,i,j,:] @ W)[o] + bias[o] )
// Linearity rewrite:
//   y[b,i,f]   = sum_j adj[b,i,j] * concat(s1,s2)[b,i,j,f]     (gated gather-reduce)
//   out[b,i,o] = relu( sum_f y[f]*W[f,o] + bias[o]*rowsum(adj) )
//
// B=16, M=128, FE=64 (concat -> 128), FO=128.
// R3 skeleton (best so far): 256 threads, 8 warps, one warp per row, RPB=8,
// grid 256. Change vs R3: gather uses a two-deep pipeline of 8-wide batches
// (effective MLP-16) -> dependent DRAM rounds per row drop from 4 to ~2.

#define BM 128
#define FE 64
#define FT 128
#define FO 128
#define RPB 8     // rows per block

__global__ __launch_bounds__(256, 2)
void gcn_fused5(const float* __restrict__ s1,
                const float* __restrict__ s2,
                const float* __restrict__ adj,
                const float* __restrict__ W,
                const float* __restrict__ bias,
                float* __restrict__ out)
{
    __shared__ int   jidx_s[RPB][BM];
    __shared__ float aval_s[RPB][BM];
    __shared__ float y_s[RPB][FT];
    __shared__ float rowsum_s[RPB];

    const int tid  = threadIdx.x;     // 0..255
    const int lane = tid & 31;
    const int w    = tid >> 5;        // warp id = local row id, 0..7
    const int bi0  = blockIdx.x * RPB;
    const int row  = bi0 + w;         // flat b*M + i

    // ---- Phase 1a: adjacency load + warp-prefix compaction ----
    const float4 av = *(const float4*)(adj + (size_t)row * BM + lane * 4);
    int   cnt  = 0;
    float rsum = 0.0f;
    {
        const unsigned lt = (1u << lane) - 1u;
        #pragma unroll
        for (int q = 0; q < 4; q++) {
            const float a = (q == 0) ? av.x : (q == 1) ? av.y : (q == 2) ? av.z : av.w;
            const unsigned m = __ballot_sync(0xFFFFFFFFu, a != 0.0f);
            if (a != 0.0f) {
                const int pos = cnt + __popc(m & lt);
                jidx_s[w][pos] = lane * 4 + q;
                aval_s[w][pos] = a;
            }
            cnt  += __popc(m);
            rsum += a;
        }
        #pragma unroll
        for (int off = 16; off > 0; off >>= 1)
            rsum += __shfl_xor_sync(0xFFFFFFFFu, rsum, off);
        if (lane == 0) rowsum_s[w] = rsum;
    }
    __syncwarp();

    // ---- Phase 1b: gather-reduce, two-deep pipeline of 8-wide batches ----
    // lane -> one float4 of the 128-wide concat row:
    //   lanes 0..15  -> s1, float4 idx = lane        (features 0..63)
    //   lanes 16..31 -> s2, float4 idx = lane - 16   (features 64..127)
    const float4* base4;
    {
        const size_t row0 = (size_t)row * (size_t)(BM * FE);
        base4 = (lane < 16) ? ((const float4*)(s1 + row0) + lane)
                            : ((const float4*)(s2 + row0) + (lane - 16));
    }
    const int jsafe = jidx_s[w][0];   // dummy target for invalid slots (L1 hit)

    float4 v0[8], v1[8];

    // issue batch starting at slot k0 into buf (predicated by cnt)
    #define ISSUE(buf, k0)                                              \
        {                                                               \
            _Pragma("unroll")                                           \
            for (int t = 0; t < 8; t++) {                               \
                const int  kk = (k0) + t;                               \
                const int  j  = (kk < cnt) ? jidx_s[w][kk] : jsafe;     \
                buf[t] = __ldg(base4 + (size_t)j * 16);                 \
            }                                                           \
        }

    // consume batch starting at slot k0 from buf (a=0 for invalid slots)
    #define CONSUME(buf, k0)                                            \
        {                                                               \
            _Pragma("unroll")                                           \
            for (int t = 0; t < 8; t++) {                               \
                const int   kk = (k0) + t;                              \
                const float a  = (kk < cnt) ? aval_s[w][kk] : 0.0f;     \
                acc.x = fmaf(a, buf[t].x, acc.x);                       \
                acc.y = fmaf(a, buf[t].y, acc.y);                       \
                acc.z = fmaf(a, buf[t].z, acc.z);                       \
                acc.w = fmaf(a, buf[t].w, acc.w);                       \
            }                                                           \
        }

    float4 acc = make_float4(0.f, 0.f, 0.f, 0.f);

    ISSUE(v0, 0)
    ISSUE(v1, 8)
    for (int k0 = 0; k0 < cnt; k0 += 16) {
        CONSUME(v0, k0)
        ISSUE(v0, k0 + 16)
        CONSUME(v1, k0 + 8)
        ISSUE(v1, k0 + 24)
    }
    #undef ISSUE
    #undef CONSUME

    {
        const int fb = (lane < 16) ? (lane * 4) : (FE + (lane - 16) * 4);
        *(float4*)&y_s[w][fb] = acc;
    }
    __syncthreads();

    // ---- Phase 2: out[r,o] = relu( y[r,:] @ W[:,o] + bias[o]*rowsum[r] ) ----
    // 256 threads: o = tid&127, group g = tid>>7 owns 4 rows (W reuse x8/block).
    const int o  = tid & (FO - 1);
    const int g  = tid >> 7;          // 0 or 1
    const int r0 = g * 4;

    float accO[4];
    {
        const float bo = __ldg(bias + o);
        #pragma unroll
        for (int q = 0; q < 4; q++) accO[q] = bo * rowsum_s[r0 + q];
    }

    #pragma unroll 8
    for (int f = 0; f < FT; f += 4) {
        const float w0 = __ldg(W + (f + 0) * FO + o);
        const float w1 = __ldg(W + (f + 1) * FO + o);
        const float w2 = __ldg(W + (f + 2) * FO + o);
        const float w3 = __ldg(W + (f + 3) * FO + o);
        #pragma unroll
        for (int q = 0; q < 4; q++) {
            const float4 y = *(const float4*)&y_s[r0 + q][f];
            accO[q] = fmaf(y.x, w0, accO[q]);
            accO[q] = fmaf(y.y, w1, accO[q]);
            accO[q] = fmaf(y.z, w2, accO[q]);
            accO[q] = fmaf(y.w, w3, accO[q]);
        }
    }

    #pragma unroll
    for (int q = 0; q < 4; q++)
        out[(size_t)(bi0 + r0 + q) * FO + o] = fmaxf(accO[q], 0.0f);
}

extern "C" void kernel_launch(void* const* d_in, const int* in_sizes, int n_in,
                              void* d_out, int out_size)
{
    const float* s1   = (const float*)d_in[0];  // (16,128,128,64)
    const float* s2   = (const float*)d_in[1];  // (16,128,128,64)
    const float* adj  = (const float*)d_in[2];  // (16,128,128)
    const float* W    = (const float*)d_in[3];  // (128,128)
    const float* bias = (const float*)d_in[4];  // (128,)
    float* out = (float*)d_out;                 // (16,128,128)

    gcn_fused5<<<(16 * 128) / RPB, 256>>>(s1, s2, adj, W, bias, out);
}